// round 17
// baseline (speedup 1.0000x reference)
#include <cuda_runtime.h>
#include <cuda_bf16.h>
#include <math.h>

#define NB      4
#define SEQ     8192
#define DM      512
#define NH      8
#define DH      64
#define NM      256
#define LG      32
#define BH      32          // NB*NH
#define TRIPLE  1536
#define ROWS    32768       // NB*SEQ

// ---------------- scratch (device globals; no allocations allowed) -------
__device__ float g_q [(size_t)BH * SEQ * DH];         // packed tf32, pre-scaled by dh^-0.5
__device__ float g_k [(size_t)BH * SEQ * DH];
__device__ float g_v [(size_t)BH * SEQ * DH];
__device__ float g_ql[BH * NM * DH];
__device__ float g_kl[BH * NM * DH];
__device__ float g_X [BH * NM * NM];                  // attn2 (tf32 after softmax)
__device__ float g_Za[BH * NM * NM];
__device__ float g_Zb[BH * NM * NM];
__device__ float g_XZ[BH * NM * NM];
__device__ float g_T1[BH * NM * NM];
__device__ float g_T2[BH * NM * NM];
__device__ float g_C2[BH * NM * DH];                  // softmax(sim3) @ v
__device__ float g_Cm[BH * NM * DH];                  // Z @ C2
__device__ float g_Y [(size_t)ROWS * DM];             // step0: x_r; step8+: pre-out-proj
__device__ float g_wr[TRIPLE * DM + DM * DM];         // rounded w_qkv | w_out
__device__ unsigned int g_mx[2];
__device__ unsigned int g_bar[BH];                    // pinv inter-CTA barrier

// ---------------- helpers ----------------
__device__ __forceinline__ float to_tf32(float x) {
    unsigned u; asm("cvt.rna.tf32.f32 %0, %1;" : "=r"(u) : "f"(x));
    return __uint_as_float(u);
}
__device__ __forceinline__ void mma8(float4& d, float a0, float a1, float a2, float a3,
                                     float b0, float b1) {
    asm volatile(
        "mma.sync.aligned.m16n8k8.row.col.f32.tf32.tf32.f32 "
        "{%0,%1,%2,%3}, {%4,%5,%6,%7}, {%8,%9}, {%0,%1,%2,%3};"
        : "+f"(d.x), "+f"(d.y), "+f"(d.z), "+f"(d.w)
        : "r"(__float_as_uint(a0)), "r"(__float_as_uint(a1)),
          "r"(__float_as_uint(a2)), "r"(__float_as_uint(a3)),
          "r"(__float_as_uint(b0)), "r"(__float_as_uint(b1)));
}
__device__ __forceinline__ void cpa16(void* s, const void* g) {
    unsigned sa = (unsigned)__cvta_generic_to_shared(s);
    asm volatile("cp.async.cg.shared.global [%0], [%1], 16;" :: "r"(sa), "l"(g));
}
__device__ __forceinline__ void cpa16z(void* s, const void* g, bool ok) {
    unsigned sa = (unsigned)__cvta_generic_to_shared(s);
    int sz = ok ? 16 : 0;
    asm volatile("cp.async.cg.shared.global [%0], [%1], 16, %2;" :: "r"(sa), "l"(g), "r"(sz));
}

// pre-round true inputs: x -> g_Y, w_qkv|w_out -> g_wr
__global__ void k_round3(const float* __restrict__ x, const float* __restrict__ wq,
                         const float* __restrict__ wo) {
    int i = blockIdx.x * 256 + threadIdx.x;
    const int NX = (ROWS * DM) >> 2;        // 4194304
    const int NW = (TRIPLE * DM) >> 2;      // 196608
    float4 v; float4* dst;
    if (i < NX)            { v = ((const float4*)x)[i];            dst = (float4*)g_Y + i; }
    else if (i < NX + NW)  { int j = i - NX;      v = ((const float4*)wq)[j]; dst = (float4*)g_wr + j; }
    else                   { int j = i - NX - NW; v = ((const float4*)wo)[j];
                             dst = (float4*)(g_wr + TRIPLE * DM) + j; }
    float4 r; r.x = to_tf32(v.x); r.y = to_tf32(v.y); r.z = to_tf32(v.z); r.w = to_tf32(v.w);
    *dst = r;
}

// =====================================================================
// TF32 tensor-core GEMM, cp.async 3-stage pipeline. Operands in memory are
// already exactly-tf32 (producer-rounded), so fragments feed MMA raw.
// BM in {128,256}, BN in {128,64}. BK=16. Warp M-tile = BM/4.
// EPI==0: C = alpha*(A@B[^T]) + beta*D (+bias); RC rounds stores to tf32.
// EPI==1: qkv scatter epilogue into q/k/v (q scaled by 0.125), rounded.
// =====================================================================
template<int BM, int BN, int WARPS_N, bool TRANSB, int EPI, int RC>
__global__ __launch_bounds__(128 * WARPS_N)
void t_gemm(const float* __restrict__ A, int lda, long long sA,
            const float* __restrict__ B, int ldb, long long sB,
            const float* __restrict__ D, long long sD,
            const float* __restrict__ bias,
            float* __restrict__ C, int ldc, long long sC,
            int K, float alpha, float beta, int ksplit,
            float* __restrict__ qp, float* __restrict__ kp, float* __restrict__ vp)
{
    constexpr int NT   = 128 * WARPS_N;
    constexpr int MT   = BM / 64;         // m16 tiles per warp
    constexpr int ASTG = BM * 20;
    constexpr int BSTG = TRANSB ? BN * 20 : 16 * (BN + 8);
    constexpr int ACH  = 4 * BM / NT;     // 16B chunks per thread per stage
    constexpr int BCH  = 4 * BN / NT;
    extern __shared__ float smp[];
    float* As = smp;
    float* Bs = smp + 3 * ASTG;

    const int tid = threadIdx.x;
    const int z = blockIdx.z;
    const int bh = z / ksplit, sk = z - bh * ksplit;
    const float* Ab = A + (size_t)bh * sA + (size_t)blockIdx.y * BM * lda + (size_t)sk * K;
    const float* Bb;
    if (TRANSB) Bb = B + (size_t)bh * sB + (size_t)blockIdx.x * BN * ldb + (size_t)sk * K;
    else        Bb = B + (size_t)bh * sB + (size_t)sk * K * ldb + blockIdx.x * BN;

    const int lane = tid & 31, g = lane >> 2, tg = lane & 3;
    const int wid = tid >> 5, wm = wid & 3, wn = wid >> 2;

    auto issue = [&](int kb, int st) {
        #pragma unroll
        for (int i = 0; i < ACH; i++) {
            int id = tid + i * NT;
            int row = id >> 2, c4 = id & 3;
            cpa16(&As[st * ASTG + row * 20 + c4 * 4],
                  Ab + (size_t)row * lda + kb * 16 + c4 * 4);
        }
        #pragma unroll
        for (int i = 0; i < BCH; i++) {
            int id = tid + i * NT;
            if constexpr (TRANSB) {
                int row = id >> 2, c4 = id & 3;
                cpa16(&Bs[st * BSTG + row * 20 + c4 * 4],
                      Bb + (size_t)row * ldb + kb * 16 + c4 * 4);
            } else {
                int kr = id / (BN / 4), n4 = id % (BN / 4);
                cpa16(&Bs[st * BSTG + kr * (BN + 8) + n4 * 4],
                      Bb + (size_t)(kb * 16 + kr) * ldb + n4 * 4);
            }
        }
        asm volatile("cp.async.commit_group;");
    };

    float4 acc[MT][8];
    #pragma unroll
    for (int i = 0; i < MT; i++)
        #pragma unroll
        for (int j = 0; j < 8; j++) acc[i][j] = make_float4(0.f, 0.f, 0.f, 0.f);

    const int kblocks = K >> 4;
    issue(0, 0); issue(1, 1);
    for (int kb = 0; kb < kblocks; kb++) {
        if (kb + 1 < kblocks) { asm volatile("cp.async.wait_group 1;"); }
        else                  { asm volatile("cp.async.wait_group 0;"); }
        __syncthreads();
        if (kb + 2 < kblocks) issue(kb + 2, (kb + 2) % 3);
        const float* Ac = As + (kb % 3) * ASTG;
        const float* Bc = Bs + (kb % 3) * BSTG;
        #pragma unroll
        for (int s8 = 0; s8 < 16; s8 += 8) {
            float a[MT][4];
            #pragma unroll
            for (int mt = 0; mt < MT; mt++) {
                const int Rm = wm * (BM / 4) + mt * 16 + g;
                a[mt][0] = Ac[Rm * 20 + s8 + tg];
                a[mt][1] = Ac[(Rm + 8) * 20 + s8 + tg];
                a[mt][2] = Ac[Rm * 20 + s8 + tg + 4];
                a[mt][3] = Ac[(Rm + 8) * 20 + s8 + tg + 4];
            }
            #pragma unroll
            for (int nt = 0; nt < 8; nt++) {
                const int c = wn * 64 + nt * 8 + g;
                float b0, b1;
                if constexpr (TRANSB) {
                    b0 = Bc[c * 20 + s8 + tg];
                    b1 = Bc[c * 20 + s8 + tg + 4];
                } else {
                    b0 = Bc[(s8 + tg) * (BN + 8) + c];
                    b1 = Bc[(s8 + tg + 4) * (BN + 8) + c];
                }
                #pragma unroll
                for (int mt = 0; mt < MT; mt++)
                    mma8(acc[mt][nt], a[mt][0], a[mt][1], a[mt][2], a[mt][3], b0, b1);
            }
        }
    }

    // epilogue
    const int r00 = blockIdx.y * BM + wm * (BM / 4);
    #pragma unroll
    for (int mt = 0; mt < MT; mt++) {
        #pragma unroll
        for (int nt = 0; nt < 8; nt++) {
            const int r0 = r00 + mt * 16 + g;
            const int cb = blockIdx.x * BN + wn * 64 + nt * 8 + tg * 2;
            float4 v = acc[mt][nt];
            if constexpr (EPI == 1) {
                const int which = cb >> 9, rem = cb & 511;
                const int h = rem >> 6, d = rem & 63;
                const float s = (which == 0) ? 0.125f : 1.0f;
                float* dst = (which == 0) ? qp : ((which == 1) ? kp : vp);
                int b = r0 >> 13, ii = r0 & 8191;
                float2 lo; lo.x = to_tf32(v.x * s); lo.y = to_tf32(v.y * s);
                *(float2*)&dst[(((size_t)(b * 8 + h) * 8192 + ii) << 6) + d] = lo;
                const int r1 = r0 + 8; b = r1 >> 13; ii = r1 & 8191;
                float2 hi; hi.x = to_tf32(v.z * s); hi.y = to_tf32(v.w * s);
                *(float2*)&dst[(((size_t)(b * 8 + h) * 8192 + ii) << 6) + d] = hi;
            } else {
                float* Cb = C + (size_t)z * sC;
                const float* Db = D + (size_t)bh * sD;
                float2 lo, hi;
                lo.x = alpha * v.x; lo.y = alpha * v.y;
                hi.x = alpha * v.z; hi.y = alpha * v.w;
                if (beta != 0.f) {
                    float2 dlo = *(const float2*)&Db[(size_t)r0 * ldc + cb];
                    float2 dhi = *(const float2*)&Db[(size_t)(r0 + 8) * ldc + cb];
                    lo.x += beta * dlo.x; lo.y += beta * dlo.y;
                    hi.x += beta * dhi.x; hi.y += beta * dhi.y;
                }
                if (bias) {
                    float2 bv = *(const float2*)&bias[cb];
                    lo.x += bv.x; lo.y += bv.y; hi.x += bv.x; hi.y += bv.y;
                }
                if constexpr (RC) {
                    lo.x = to_tf32(lo.x); lo.y = to_tf32(lo.y);
                    hi.x = to_tf32(hi.x); hi.y = to_tf32(hi.y);
                }
                *(float2*)&Cb[(size_t)r0 * ldc + cb] = lo;
                *(float2*)&Cb[(size_t)(r0 + 8) * ldc + cb] = hi;
            }
        }
    }
}

// =====================================================================
// Persistent pinv: 24 chained GEMM steps, one launch.
// 256 CTAs, 8 per bh (128x64 tiles). 2 CTAs/SM residency keeps barrier safe.
// =====================================================================
__global__ __launch_bounds__(256)
void k_pinv() {
    constexpr int ASTG = 128 * 20;
    constexpr int BSTG = 16 * 72;
    extern __shared__ float smp[];
    float* As = smp;
    float* Bs = smp + 3 * ASTG;

    const int bh = blockIdx.x >> 3;
    const int oct = blockIdx.x & 7;
    const int by = oct >> 2, bx = oct & 3;
    const int tid = threadIdx.x;
    const int lane = tid & 31, g = lane >> 2, tg = lane & 3;
    const int wid = tid >> 5, wm = wid & 3, wn = wid >> 2;   // wn in {0,1}

    float* Xp  = g_X  + (size_t)bh * 65536;
    float* XZp = g_XZ + (size_t)bh * 65536;
    float* T1p = g_T1 + (size_t)bh * 65536;
    float* T2p = g_T2 + (size_t)bh * 65536;
    float* Zc  = g_Za + (size_t)bh * 65536;
    float* Zn  = g_Zb + (size_t)bh * 65536;
    unsigned int* bar = &g_bar[bh];

    for (int s = 0; s < 24; s++) {
        const int sub = s & 3;
        const float *Asrc, *Bsrc, *Dsrc; float* Cdst; float alpha, beta;
        if (sub == 0)      { Asrc = Xp;  Bsrc = Zc;  Dsrc = 0;   Cdst = XZp; alpha = 1.f;    beta = 0.f;   }
        else if (sub == 1) { Asrc = XZp; Bsrc = XZp; Dsrc = XZp; Cdst = T1p; alpha = -1.f;   beta = 7.f;   }
        else if (sub == 2) { Asrc = XZp; Bsrc = T1p; Dsrc = XZp; Cdst = T2p; alpha = -1.f;   beta = 15.f;  }
        else               { Asrc = Zc;  Bsrc = T2p; Dsrc = Zc;  Cdst = Zn;  alpha = -0.25f; beta = 3.25f; }

        const float* Ab = Asrc + (size_t)by * 128 * 256;
        const float* Bb = Bsrc + bx * 64;

        auto issue = [&](int kb, int st) {
            #pragma unroll
            for (int i = 0; i < 2; i++) {
                int id = tid + i * 256;
                int row = id >> 2, c4 = id & 3;
                cpa16(&As[st * ASTG + row * 20 + c4 * 4],
                      Ab + (size_t)row * 256 + kb * 16 + c4 * 4);
            }
            {
                int kr = tid >> 4, n4 = tid & 15;
                cpa16(&Bs[st * BSTG + kr * 72 + n4 * 4],
                      Bb + (size_t)(kb * 16 + kr) * 256 + n4 * 4);
            }
            asm volatile("cp.async.commit_group;");
        };

        float4 acc[2][4];
        #pragma unroll
        for (int i = 0; i < 2; i++)
            #pragma unroll
            for (int j = 0; j < 4; j++) acc[i][j] = make_float4(0.f, 0.f, 0.f, 0.f);

        issue(0, 0); issue(1, 1);
        for (int kb = 0; kb < 16; kb++) {
            if (kb + 1 < 16) { asm volatile("cp.async.wait_group 1;"); }
            else             { asm volatile("cp.async.wait_group 0;"); }
            __syncthreads();
            if (kb + 2 < 16) issue(kb + 2, (kb + 2) % 3);
            const float* Ac = As + (kb % 3) * ASTG;
            const float* Bc = Bs + (kb % 3) * BSTG;
            #pragma unroll
            for (int s8 = 0; s8 < 16; s8 += 8) {
                float a[2][4];
                #pragma unroll
                for (int mt = 0; mt < 2; mt++) {
                    const int Rm = wm * 32 + mt * 16 + g;
                    a[mt][0] = Ac[Rm * 20 + s8 + tg];
                    a[mt][1] = Ac[(Rm + 8) * 20 + s8 + tg];
                    a[mt][2] = Ac[Rm * 20 + s8 + tg + 4];
                    a[mt][3] = Ac[(Rm + 8) * 20 + s8 + tg + 4];
                }
                #pragma unroll
                for (int nt = 0; nt < 4; nt++) {
                    const int c = wn * 32 + nt * 8 + g;
                    float b0 = Bc[(s8 + tg) * 72 + c];
                    float b1 = Bc[(s8 + tg + 4) * 72 + c];
                    #pragma unroll
                    for (int mt = 0; mt < 2; mt++)
                        mma8(acc[mt][nt], a[mt][0], a[mt][1], a[mt][2], a[mt][3], b0, b1);
                }
            }
        }

        // epilogue (D via __ldcg; store rounded)
        #pragma unroll
        for (int mt = 0; mt < 2; mt++) {
            #pragma unroll
            for (int nt = 0; nt < 4; nt++) {
                const int r0 = by * 128 + wm * 32 + mt * 16 + g;
                const int cb = bx * 64 + wn * 32 + nt * 8 + tg * 2;
                float4 v = acc[mt][nt];
                float2 lo, hi;
                lo.x = alpha * v.x; lo.y = alpha * v.y;
                hi.x = alpha * v.z; hi.y = alpha * v.w;
                if (beta != 0.f) {
                    float2 dlo = __ldcg((const float2*)&Dsrc[(size_t)r0 * 256 + cb]);
                    float2 dhi = __ldcg((const float2*)&Dsrc[(size_t)(r0 + 8) * 256 + cb]);
                    lo.x += beta * dlo.x; lo.y += beta * dlo.y;
                    hi.x += beta * dhi.x; hi.y += beta * dhi.y;
                }
                lo.x = to_tf32(lo.x); lo.y = to_tf32(lo.y);
                hi.x = to_tf32(hi.x); hi.y = to_tf32(hi.y);
                *(float2*)&Cdst[(size_t)r0 * 256 + cb] = lo;
                *(float2*)&Cdst[(size_t)(r0 + 8) * 256 + cb] = hi;
            }
        }

        // per-bh barrier: all 8 CTAs finish step s before anyone starts s+1
        __threadfence();
        __syncthreads();
        if (tid == 0) {
            asm volatile("red.release.gpu.global.add.u32 [%0], %1;"
                         :: "l"(bar), "r"(1u) : "memory");
            const unsigned target = 8u * (unsigned)(s + 1);
            unsigned cur;
            do {
                __nanosleep(64);
                asm volatile("ld.acquire.gpu.global.u32 %0, [%1];" : "=r"(cur) : "l"(bar));
            } while (cur < target);
        }
        __syncthreads();

        if (sub == 3) { float* t = Zc; Zc = Zn; Zn = t; }
    }
}

// =====================================================================
// Flash-style fused sim3 path (ql/k/v producer-rounded; no fill cvt)
// =====================================================================
#define FA3_SMEM (207872)
__global__ __launch_bounds__(256)
void k_fattn3(const float* __restrict__ qlg, const float* __restrict__ kg,
              const float* __restrict__ vg, float* __restrict__ c2)
{
    extern __shared__ float sm[];
    float* Qs = sm;                         // [kk<64][g<8][x<16]
    float* Ks = sm + 8192;                  // 2 stages, [c<128][68]
    float* Vs = sm + 8192 + 2 * 8704;       // 2 stages, [c<128][68]
    float* Ps = sm + 8192 + 4 * 8704;       // [row<64][132]
    float* Mp = Ps + 8448;                  // [4][64]
    float* Lp = Mp + 256;                   // [4][64]

    const int bh = blockIdx.y;
    const int i0 = blockIdx.x * 64;
    const int tid = threadIdx.x;
    const int lane = tid & 31, g = lane >> 2, tg = lane & 3;
    const int wid = tid >> 5, wm = wid & 1, wn = wid >> 1;
    const int sw = tg << 2;

    const float* kb = kg + (size_t)bh * SEQ * DH;
    const float* vb = vg + (size_t)bh * SEQ * DH;

    auto issue = [&](int j, int st) {
        const int cb = j * 128;
        #pragma unroll
        for (int i = 0; i < 8; i++) {
            int t4 = tid + i * 256;
            int row = t4 >> 4, q4 = (t4 & 15) << 2;
            cpa16(&Ks[st * 8704 + row * 68 + q4], kb + (size_t)(cb + row) * 64 + q4);
        }
        #pragma unroll
        for (int i = 0; i < 8; i++) {
            int t4 = tid + i * 256;
            int row = t4 >> 4, q4 = (t4 & 15) << 2;
            cpa16(&Vs[st * 8704 + row * 68 + q4], vb + (size_t)(cb + row) * 64 + q4);
        }
        asm volatile("cp.async.commit_group;");
    };

    issue(0, 0);

    const float* qb = qlg + ((size_t)bh * NM + i0) * 64;
    #pragma unroll
    for (int i = 0; i < 4; i++) {
        int t4 = tid + i * 256; int row = t4 >> 4, kq = (t4 & 15) << 2;
        float4 v = *(const float4*)(qb + row * 64 + kq);
        float vv[4] = {v.x, v.y, v.z, v.w};
        #pragma unroll
        for (int j = 0; j < 4; j++) {
            int kk = kq + j;
            Qs[kk * 128 + (row & 7) * 16 + ((row >> 3) ^ ((kk & 3) << 2))] = vv[j];
        }
    }

    float4 acc2[2][2];
    #pragma unroll
    for (int i = 0; i < 2; i++)
        #pragma unroll
        for (int j = 0; j < 2; j++) acc2[i][j] = make_float4(0.f, 0.f, 0.f, 0.f);
    float Mrun[4] = {-1e30f, -1e30f, -1e30f, -1e30f};
    float Lrun[4] = {0.f, 0.f, 0.f, 0.f};

    for (int jt = 0; jt < SEQ / 128; jt++) {
        const int cur = jt & 1;
        if (jt + 1 < SEQ / 128) {
            issue(jt + 1, cur ^ 1);
            asm volatile("cp.async.wait_group 1;");
        } else {
            asm volatile("cp.async.wait_group 0;");
        }
        __syncthreads();

        const float* Kc = Ks + cur * 8704;
        const float* Vc = Vs + cur * 8704;

        float4 acc1[2][4];
        #pragma unroll
        for (int i = 0; i < 2; i++)
            #pragma unroll
            for (int j = 0; j < 4; j++) acc1[i][j] = make_float4(0.f, 0.f, 0.f, 0.f);
        #pragma unroll
        for (int s8 = 0; s8 < 64; s8 += 8) {
            const int k0 = s8 + tg;
            float4 aLo = *(const float4*)&Qs[k0 * 128 + g * 16 + ((wm * 4) ^ sw)];
            float4 aHi = *(const float4*)&Qs[(k0 + 4) * 128 + g * 16 + ((wm * 4) ^ sw)];
            float am[2][4] = {{aLo.x, aLo.y, aHi.x, aHi.y}, {aLo.z, aLo.w, aHi.z, aHi.w}};
            #pragma unroll
            for (int nt = 0; nt < 4; nt++) {
                const float* kr = Kc + (wn * 32 + nt * 8 + g) * 68;
                float b0 = kr[k0], b1 = kr[k0 + 4];
                #pragma unroll
                for (int mt = 0; mt < 2; mt++)
                    mma8(acc1[mt][nt], am[mt][0], am[mt][1], am[mt][2], am[mt][3], b0, b1);
            }
        }

        float tmax[4];
        #pragma unroll
        for (int t = 0; t < 4; t++) {
            const int mt = t >> 1; const bool hi = t & 1;
            float m = -1e30f;
            #pragma unroll
            for (int nt = 0; nt < 4; nt++) {
                float4 a = acc1[mt][nt];
                m = fmaxf(m, hi ? fmaxf(a.z, a.w) : fmaxf(a.x, a.y));
            }
            m = fmaxf(m, __shfl_xor_sync(0xffffffffu, m, 1));
            m = fmaxf(m, __shfl_xor_sync(0xffffffffu, m, 2));
            tmax[t] = m;
        }
        if (tg == 0) {
            #pragma unroll
            for (int t = 0; t < 4; t++) Mp[wn * 64 + wm * 32 + 8 * t + g] = tmax[t];
        }
        __syncthreads();

        float f[4];
        #pragma unroll
        for (int t = 0; t < 4; t++) {
            const int rl = wm * 32 + 8 * t + g;
            float tm = fmaxf(fmaxf(Mp[rl], Mp[64 + rl]),
                             fmaxf(Mp[128 + rl], Mp[192 + rl]));
            float Mn = fmaxf(Mrun[t], tm);
            f[t] = __expf(Mrun[t] - Mn);
            Mrun[t] = Mn;
        }
        #pragma unroll
        for (int mt2 = 0; mt2 < 2; mt2++)
            #pragma unroll
            for (int nt2 = 0; nt2 < 2; nt2++) {
                acc2[mt2][nt2].x *= f[2 * mt2];     acc2[mt2][nt2].y *= f[2 * mt2];
                acc2[mt2][nt2].z *= f[2 * mt2 + 1]; acc2[mt2][nt2].w *= f[2 * mt2 + 1];
            }
        #pragma unroll
        for (int t = 0; t < 4; t++) {
            const int mt = t >> 1; const bool hi = t & 1;
            const int rl = wm * 32 + 8 * t + g;
            const float M = Mrun[t];
            float s = 0.f;
            #pragma unroll
            for (int nt = 0; nt < 4; nt++) {
                float4 a = acc1[mt][nt];
                float v0 = hi ? a.z : a.x, v1 = hi ? a.w : a.y;
                float e0 = __expf(v0 - M), e1 = __expf(v1 - M);
                s += e0 + e1;
                int c0 = wn * 32 + nt * 8 + 2 * tg;
                Ps[rl * 132 + c0] = e0;
                Ps[rl * 132 + c0 + 1] = e1;
            }
            s += __shfl_xor_sync(0xffffffffu, s, 1);
            s += __shfl_xor_sync(0xffffffffu, s, 2);
            if (tg == 0) Lp[wn * 64 + rl] = s;
        }
        __syncthreads();
        #pragma unroll
        for (int t = 0; t < 4; t++) {
            const int rl = wm * 32 + 8 * t + g;
            Lrun[t] = Lrun[t] * f[t] + (Lp[rl] + Lp[64 + rl] + Lp[128 + rl] + Lp[192 + rl]);
        }

        #pragma unroll 4
        for (int s8 = 0; s8 < 128; s8 += 8) {
            const int k0 = s8 + tg, k1 = k0 + 4;
            float a_[2][4], b_[2][2];
            #pragma unroll
            for (int mt2 = 0; mt2 < 2; mt2++) {
                const int r0 = wm * 32 + 16 * mt2 + g;
                a_[mt2][0] = Ps[r0 * 132 + k0];
                a_[mt2][1] = Ps[(r0 + 8) * 132 + k0];
                a_[mt2][2] = Ps[r0 * 132 + k1];
                a_[mt2][3] = Ps[(r0 + 8) * 132 + k1];
            }
            #pragma unroll
            for (int nt2 = 0; nt2 < 2; nt2++) {
                const int c = wn * 16 + nt2 * 8 + g;
                b_[nt2][0] = Vc[k0 * 68 + c];
                b_[nt2][1] = Vc[k1 * 68 + c];
            }
            #pragma unroll
            for (int mt2 = 0; mt2 < 2; mt2++)
                #pragma unroll
                for (int nt2 = 0; nt2 < 2; nt2++)
                    mma8(acc2[mt2][nt2], a_[mt2][0], a_[mt2][1], a_[mt2][2], a_[mt2][3],
                         b_[nt2][0], b_[nt2][1]);
        }
        __syncthreads();
    }

    float invL[4];
    #pragma unroll
    for (int t = 0; t < 4; t++) invL[t] = 1.f / Lrun[t];
    float* ob = c2 + ((size_t)bh * NM + i0) * 64;
    #pragma unroll
    for (int mt2 = 0; mt2 < 2; mt2++) {
        #pragma unroll
        for (int nt2 = 0; nt2 < 2; nt2++) {
            const int c = wn * 16 + nt2 * 8 + 2 * tg;
            const int r0 = wm * 32 + 16 * mt2 + g;
            float4 v = acc2[mt2][nt2];
            float2 lo; lo.x = to_tf32(v.x * invL[2 * mt2]);     lo.y = to_tf32(v.y * invL[2 * mt2]);
            float2 hi; hi.x = to_tf32(v.z * invL[2 * mt2 + 1]); hi.y = to_tf32(v.w * invL[2 * mt2 + 1]);
            *(float2*)&ob[(size_t)r0 * 64 + c] = lo;
            *(float2*)&ob[(size_t)(r0 + 8) * 64 + c] = hi;
        }
    }
}

// =====================================================================
// Fused attn1 path + depthwise-conv residual + transpose into Y (rounded).
// Cm read directly from L2 via __ldg (no Cs tile) -> 104448 B smem, 2 CTAs/SM.
// smem: Qs[64][68] (later Vw[96][64]+w) | Ks[256][68] / Ps[64][260] / Osm[64][68] | red
// =====================================================================
#define FA1_SMEM (104448)
__global__ __launch_bounds__(256)
void k_fattn1(const float* __restrict__ qg, const float* __restrict__ klg,
              const float* __restrict__ cmg, const float* __restrict__ vg,
              const float* __restrict__ wres, float* __restrict__ Yg)
{
    extern __shared__ float sm[];
    float* Qs   = sm;                    // [64][68]; later Vw[96][64] + w[33]
    float* Ks   = sm + 8192;             // [256][68] = 17408
    float* Ps   = sm + 8192;             // [64][260] = 16640 (aliases Ks)
    float* Osm  = sm + 8192;             // [64][68] (aliases Ps after stage 2)
    float* Mred = sm + 25600;            // [4][64]
    float* Lred = Mred + 256;            // [4][64]

    const int bh = blockIdx.y, b = bh >> 3, h = bh & 7;
    const int i0 = blockIdx.x * 64;
    const int tid = threadIdx.x;
    const int lane = tid & 31, g = lane >> 2, tg = lane & 3;
    const int wid = tid >> 5, wm = wid & 1, wn = wid >> 1;

    // fills: pure cp.async into padded row layouts (operands already tf32)
    const float* qb = qg + ((size_t)bh * SEQ + i0) * 64;
    #pragma unroll
    for (int i = 0; i < 4; i++) {
        int id = tid + i * 256; int row = id >> 4, d4 = (id & 15) << 2;
        cpa16(&Qs[row * 68 + d4], qb + row * 64 + d4);
    }
    const float* kb = klg + (size_t)bh * NM * 64;
    #pragma unroll
    for (int i = 0; i < 16; i++) {
        int id = tid + i * 256; int row = id >> 4, d4 = (id & 15) << 2;
        cpa16(&Ks[row * 68 + d4], kb + row * 64 + d4);
    }
    asm volatile("cp.async.commit_group;");
    asm volatile("cp.async.wait_group 0;");
    __syncthreads();

    // stage 1: scores 64x256
    float4 acc1[2][8];
    #pragma unroll
    for (int i = 0; i < 2; i++)
        #pragma unroll
        for (int j = 0; j < 8; j++) acc1[i][j] = make_float4(0.f, 0.f, 0.f, 0.f);

    #pragma unroll
    for (int s8 = 0; s8 < 64; s8 += 8) {
        const int k0 = s8 + tg;
        float a[2][4];
        #pragma unroll
        for (int mt = 0; mt < 2; mt++) {
            const int Rm = wm * 32 + mt * 16 + g;
            a[mt][0] = Qs[Rm * 68 + k0];
            a[mt][1] = Qs[(Rm + 8) * 68 + k0];
            a[mt][2] = Qs[Rm * 68 + k0 + 4];
            a[mt][3] = Qs[(Rm + 8) * 68 + k0 + 4];
        }
        #pragma unroll
        for (int nt = 0; nt < 8; nt++) {
            const int c = wn * 64 + nt * 8 + g;
            float b0 = Ks[c * 68 + k0];
            float b1 = Ks[c * 68 + k0 + 4];
            #pragma unroll
            for (int mt = 0; mt < 2; mt++)
                mma8(acc1[mt][nt], a[mt][0], a[mt][1], a[mt][2], a[mt][3], b0, b1);
        }
    }

    float rmax[4];
    #pragma unroll
    for (int t = 0; t < 4; t++) {
        const int mt = t >> 1; const bool hi = t & 1;
        float m = -1e30f;
        #pragma unroll
        for (int nt = 0; nt < 8; nt++) {
            float4 a = acc1[mt][nt];
            m = fmaxf(m, hi ? fmaxf(a.z, a.w) : fmaxf(a.x, a.y));
        }
        m = fmaxf(m, __shfl_xor_sync(0xffffffffu, m, 1));
        m = fmaxf(m, __shfl_xor_sync(0xffffffffu, m, 2));
        rmax[t] = m;
    }
    if (tg == 0) {
        #pragma unroll
        for (int t = 0; t < 4; t++) Mred[wn * 64 + 32 * wm + 8 * t + g] = rmax[t];
    }
    __syncthreads();   // stage-1 reads done: Qs/Ks regions may be reused

    // prefetch v window for conv into Qs region (dead) + conv weights
    {
        const float* vb = vg + (size_t)bh * SEQ * DH;
        #pragma unroll
        for (int i2 = 0; i2 < 6; i2++) {
            int id = tid + i2 * 256;                 // 1536 chunks = 96 rows x 16
            int j = id >> 4, d4 = (id & 15) << 2;
            int gi = i0 - 16 + j;
            bool ok = (gi >= 0 && gi < SEQ);
            cpa16z(&Qs[j * 64 + d4], vb + (size_t)(ok ? gi : 0) * 64 + d4, ok);
        }
        if (tid < 33) Qs[6144 + tid] = wres[h * 33 + tid];
        asm volatile("cp.async.commit_group;");
    }

    #pragma unroll
    for (int t = 0; t < 4; t++) {
        const int rl = 32 * wm + 8 * t + g;
        rmax[t] = fmaxf(fmaxf(Mred[rl], Mred[64 + rl]),
                        fmaxf(Mred[128 + rl], Mred[192 + rl]));
    }
    #pragma unroll
    for (int t = 0; t < 4; t++) {
        const int mt = t >> 1; const bool hi = t & 1;
        const int rl = 32 * wm + 8 * t + g;
        const float M = rmax[t];
        float s = 0.f;
        #pragma unroll
        for (int nt = 0; nt < 8; nt++) {
            float4 a = acc1[mt][nt];
            float v0 = hi ? a.z : a.x, v1 = hi ? a.w : a.y;
            float e0 = __expf(v0 - M), e1 = __expf(v1 - M);
            s += e0 + e1;
            int c0 = wn * 64 + nt * 8 + 2 * tg;
            Ps[rl * 260 + c0] = to_tf32(e0);
            Ps[rl * 260 + c0 + 1] = to_tf32(e1);
        }
        s += __shfl_xor_sync(0xffffffffu, s, 1);
        s += __shfl_xor_sync(0xffffffffu, s, 2);
        if (tg == 0) Lred[wn * 64 + rl] = s;
    }
    __syncthreads();

    // stage 2: O = P(64x256) @ Cm(256x64); B direct from L2 via __ldg
    const float* cmb = cmg + (size_t)bh * NM * 64;
    float4 acc2[2][2];
    #pragma unroll
    for (int i = 0; i < 2; i++)
        #pragma unroll
        for (int j = 0; j < 2; j++) acc2[i][j] = make_float4(0.f, 0.f, 0.f, 0.f);

    #pragma unroll 4
    for (int s8 = 0; s8 < 256; s8 += 8) {
        const int k0 = s8 + tg, k1 = k0 + 4;
        float b_[2][2];
        #pragma unroll
        for (int nt = 0; nt < 2; nt++) {
            const int c = wn * 16 + nt * 8 + g;
            b_[nt][0] = __ldg(&cmb[k0 * 64 + c]);
            b_[nt][1] = __ldg(&cmb[k1 * 64 + c]);
        }
        float a_[2][4];
        #pragma unroll
        for (int mt = 0; mt < 2; mt++) {
            const int r0 = wm * 32 + 16 * mt + g;
            a_[mt][0] = Ps[r0 * 260 + k0];
            a_[mt][1] = Ps[(r0 + 8) * 260 + k0];
            a_[mt][2] = Ps[r0 * 260 + k1];
            a_[mt][3] = Ps[(r0 + 8) * 260 + k1];
        }
        #pragma unroll
        for (int mt = 0; mt < 2; mt++)
            #pragma unroll
            for (int nt = 0; nt < 2; nt++)
                mma8(acc2[mt][nt], a_[mt][0], a_[mt][1], a_[mt][2], a_[mt][3],
                     b_[nt][0], b_[nt][1]);
    }

    float invL[4];
    #pragma unroll
    for (int t = 0; t < 4; t++) {
        const int rl = 32 * wm + 8 * t + g;
        float L = Lred[rl] + Lred[64 + rl] + Lred[128 + rl] + Lred[192 + rl];
        invL[t] = 1.f / L;
    }

    asm volatile("cp.async.wait_group 0;");
    __syncthreads();    // stage-2 reads of Ps done; Vw ready

    // stage scaled O into Osm (aliases Ps region, safe after sync)
    #pragma unroll
    for (int mt = 0; mt < 2; mt++) {
        #pragma unroll
        for (int nt = 0; nt < 2; nt++) {
            const int c = wn * 16 + nt * 8 + 2 * tg;
            const int r0 = 32 * wm + 16 * mt + g;
            float4 v = acc2[mt][nt];
            float2 lo; lo.x = v.x * invL[2 * mt]; lo.y = v.y * invL[2 * mt];
            float2 hi; hi.x = v.z * invL[2 * mt + 1]; hi.y = v.w * invL[2 * mt + 1];
            *(float2*)&Osm[r0 * 68 + c] = lo;
            *(float2*)&Osm[(r0 + 8) * 68 + c] = hi;
        }
    }
    __syncthreads();

    // conv + write to Y (transposed layout, rounded for the out-proj GEMM)
    const float* wv = Qs + 6144;
    #pragma unroll
    for (int i2 = 0; i2 < 4; i2++) {
        int l4 = tid + i2 * 256;            // 1024 float4s = 64 rows x 16
        int i = l4 >> 4, d4 = (l4 & 15) << 2;
        float4 o = *(float4*)&Osm[i * 68 + d4];
        #pragma unroll
        for (int t = 0; t < 33; t++) {
            float wt = wv[t];
            float4 vv = *(float4*)&Qs[(i + t) * 64 + d4];
            o.x += wt * vv.x; o.y += wt * vv.y; o.z += wt * vv.z; o.w += wt * vv.w;
        }
        o.x = to_tf32(o.x); o.y = to_tf32(o.y); o.z = to_tf32(o.z); o.w = to_tf32(o.w);
        *(float4*)&Yg[(size_t)(b * SEQ + i0 + i) * DM + h * 64 + d4] = o;
    }
}

// landmarks: mean over 32 consecutive tokens (rounded outputs)
__global__ void k_land() {
    int idx = blockIdx.x * blockDim.x + threadIdx.x;   // BH*NM*DH
    int d = idx & 63, i = (idx >> 6) & 255, bh = idx >> 14;
    size_t base = (size_t)bh * SEQ * DH + (size_t)i * LG * DH + d;
    float qs = 0.f, ks = 0.f;
    #pragma unroll 8
    for (int j = 0; j < LG; j++) { qs += g_q[base + j * 64]; ks += g_k[base + j * 64]; }
    g_ql[idx] = to_tf32(qs * (1.f / LG));
    g_kl[idx] = to_tf32(ks * (1.f / LG));
}

// Row softmax (in place, rounded), 256 cols, one block per row.
__global__ void k_softmax(float* __restrict__ X) {
    const size_t base = (size_t)blockIdx.x * 256;
    const int tid = threadIdx.x, lane = tid & 31, wp = tid >> 5;
    __shared__ float red[8];
    float v = X[base + tid];
    float m = v;
    #pragma unroll
    for (int off = 16; off; off >>= 1) m = fmaxf(m, __shfl_xor_sync(0xffffffffu, m, off));
    if (!lane) red[wp] = m;
    __syncthreads();
    float M = red[0];
    #pragma unroll
    for (int w = 1; w < 8; w++) M = fmaxf(M, red[w]);
    __syncthreads();
    float e = __expf(v - M);
    float s = e;
    #pragma unroll
    for (int off = 16; off; off >>= 1) s += __shfl_xor_sync(0xffffffffu, s, off);
    if (!lane) red[wp] = s;
    __syncthreads();
    float S = 0.f;
    #pragma unroll
    for (int w = 0; w < 8; w++) S += red[w];
    X[base + tid] = to_tf32(e / S);
}

// reset: g_mx and pinv barrier counters (standalone, strictly before pinv)
__global__ void k_reset() {
    if (threadIdx.x < 2) g_mx[threadIdx.x] = 0u;
    if (threadIdx.x < BH) g_bar[threadIdx.x] = 0u;
}

__global__ void k_colrowmax() {
    const int bh = blockIdx.x, tid = threadIdx.x, lane = tid & 31, wp = tid >> 5;
    __shared__ float red[8];
    const float* Xb = g_X + (size_t)bh * NM * NM;
    float cs = 0.f;
    for (int i = 0; i < NM; i++) cs += Xb[i * NM + tid];
    float m = cs;
    #pragma unroll
    for (int off = 16; off; off >>= 1) m = fmaxf(m, __shfl_xor_sync(0xffffffffu, m, off));
    if (!lane) red[wp] = m;
    __syncthreads();
    if (tid == 0) {
        float M = red[0];
        #pragma unroll
        for (int w = 1; w < 8; w++) M = fmaxf(M, red[w]);
        atomicMax(&g_mx[1], __float_as_uint(M));
    }
    __syncthreads();
    float rs = 0.f;
    const float* Xr = Xb + (size_t)tid * NM;
    for (int j = 0; j < NM; j++) rs += Xr[j];
    m = rs;
    #pragma unroll
    for (int off = 16; off; off >>= 1) m = fmaxf(m, __shfl_xor_sync(0xffffffffu, m, off));
    if (!lane) red[wp] = m;
    __syncthreads();
    if (tid == 0) {
        float M = red[0];
        #pragma unroll
        for (int w = 1; w < 8; w++) M = fmaxf(M, red[w]);
        atomicMax(&g_mx[0], __float_as_uint(M));
    }
}

__global__ void k_zinit() {
    int idx = blockIdx.x * blockDim.x + threadIdx.x;   // BH*NM*NM
    float inv = 1.f / (__uint_as_float(g_mx[0]) * __uint_as_float(g_mx[1]));
    int j = idx & 255, i = (idx >> 8) & 255, bh = idx >> 16;
    g_Za[idx] = to_tf32(g_X[(size_t)bh * NM * NM + j * NM + i] * inv);
}

// =====================================================================
extern "C" void kernel_launch(void* const* d_in, const int* in_sizes, int n_in,
                              void* d_out, int out_size) {
    const float* x     = (const float*)d_in[0];
    const float* w_qkv = (const float*)d_in[1];
    const float* w_out = (const float*)d_in[2];
    const float* b_out = (const float*)d_in[3];
    const float* w_res = (const float*)d_in[4];
    float* out = (float*)d_out;

    float *q, *k_, *v, *ql, *kl, *X, *Za, *C2, *Cm, *Y, *wr;
    cudaGetSymbolAddress((void**)&q,   g_q);
    cudaGetSymbolAddress((void**)&k_,  g_k);
    cudaGetSymbolAddress((void**)&v,   g_v);
    cudaGetSymbolAddress((void**)&ql,  g_ql);
    cudaGetSymbolAddress((void**)&kl,  g_kl);
    cudaGetSymbolAddress((void**)&X,   g_X);
    cudaGetSymbolAddress((void**)&Za,  g_Za);
    cudaGetSymbolAddress((void**)&C2,  g_C2);
    cudaGetSymbolAddress((void**)&Cm,  g_Cm);
    cudaGetSymbolAddress((void**)&Y,   g_Y);
    cudaGetSymbolAddress((void**)&wr,  g_wr);

    // dynamic smem opt-in
    const int SM_BM256 = (3 * 256 * 20 + 3 * 16 * 136) * 4;   // 87552
    const int SM_TN128 = (3 * 128 * 20 + 3 * 128 * 20) * 4;   // 61440
    const int SM_NN64  = (3 * 128 * 20 + 3 * 16 * 72) * 4;    // 44544
    cudaFuncSetAttribute(t_gemm<256, 128, 2, false, 1, 1>, cudaFuncAttributeMaxDynamicSharedMemorySize, SM_BM256);
    cudaFuncSetAttribute(t_gemm<256, 128, 2, false, 0, 0>, cudaFuncAttributeMaxDynamicSharedMemorySize, SM_BM256);
    cudaFuncSetAttribute(t_gemm<128, 128, 2, true, 0, 0>,  cudaFuncAttributeMaxDynamicSharedMemorySize, SM_TN128);
    cudaFuncSetAttribute(t_gemm<128, 64, 1, false, 0, 1>,  cudaFuncAttributeMaxDynamicSharedMemorySize, SM_NN64);
    cudaFuncSetAttribute(k_pinv,   cudaFuncAttributeMaxDynamicSharedMemorySize, SM_NN64);
    cudaFuncSetAttribute(k_fattn1, cudaFuncAttributeMaxDynamicSharedMemorySize, FA1_SMEM);
    cudaFuncSetAttribute(k_fattn3, cudaFuncAttributeMaxDynamicSharedMemorySize, FA3_SMEM);

    const float* NUL = (const float*)0;
    float* NULF = (float*)0;

    // 0. pre-round true inputs to tf32: x->g_Y, w_qkv|w_out->g_wr
    k_round3<<<17408, 256>>>(x, w_qkv, w_out);
    // 1. qkv = x_r @ w_qkv_r, scattered directly to packed q (scaled), k, v (rounded)
    t_gemm<256, 128, 2, false, 1, 1><<<dim3(TRIPLE / 128, ROWS / 256, 1), 256, SM_BM256>>>(
        Y, DM, 0LL, wr, TRIPLE, 0LL, NUL, 0LL, NUL, q, TRIPLE, 0LL,
        DM, 1.f, 0.f, 1, q, k_, v);
    // 2. landmarks
    k_land<<<(BH * NM * DH) / 256, 256>>>();
    // 3. attn2 = softmax(q_land @ k_land^T)
    t_gemm<128, 128, 2, true, 0, 0><<<dim3(2, 2, BH), 256, SM_TN128>>>(
        ql, DH, 16384LL, kl, DH, 16384LL, NUL, 0LL, NUL, X, NM, 65536LL,
        DH, 1.f, 0.f, 1, NULF, NULF, NULF);
    k_softmax<<<BH * NM, 256>>>(X);
    // 4. pinv init (standalone reset strictly before pinv)
    k_reset<<<1, 32>>>();
    k_colrowmax<<<BH, 256>>>();
    k_zinit<<<(BH * NM * NM) / 256, 256>>>();
    // 5. 6 Newton iterations, one persistent launch (result in g_Za)
    k_pinv<<<256, 256, SM_NN64>>>();
    // 6. fused flash sim3 path: C2 = softmax(ql @ k^T) @ v
    k_fattn3<<<dim3(4, BH), 256, FA3_SMEM>>>(ql, k_, v, C2);
    // 7. Cm = Z @ C2 (rounded)
    t_gemm<128, 64, 1, false, 0, 1><<<dim3(1, 2, BH), 128, SM_NN64>>>(
        Za, NM, 65536LL, C2, DH, 16384LL, NUL, 0LL, NUL, Cm, DH, 16384LL,
        NM, 1.f, 0.f, 1, NULF, NULF, NULF);
    // 8. fused: Y = softmax(q @ kl^T) @ Cm + conv33(v), transposed (rounded)
    k_fattn1<<<dim3(SEQ / 64, BH), 256, FA1_SMEM>>>(q, kl, Cm, v, w_res, Y);
    // 9. out = Y @ w_out_r + b_out (full precision store)
    t_gemm<256, 128, 2, false, 0, 0><<<dim3(DM / 128, ROWS / 256, 1), 256, SM_BM256>>>(
        Y, DM, 0LL, wr + TRIPLE * DM, DM, 0LL, NUL, 0LL, b_out, out, DM, 0LL,
        DM, 1.f, 0.f, 1, NULF, NULF, NULF);
}